// round 1
// baseline (speedup 1.0000x reference)
#include <cuda_runtime.h>
#include <math.h>

// Problem constants (fixed shape for this bench problem)
constexpr int kN   = 50000;          // nodes
constexpr int kE   = 800000;         // edges
constexpr int kEA  = kE + kN;        // edges + self loops
constexpr int kG   = 512;            // graphs
constexpr int kD   = 128;            // node dim (== H*C)
constexpr int kH   = 8;              // heads
constexpr int kEF  = 8;              // raw edge feat
constexpr int kEE  = 64;             // edge emb dim
constexpr int kL   = 4;              // layers
constexpr int kNC  = 10;             // classes
constexpr float kBNS = 0.9999950000374997f;  // (1+1e-5)^-0.5

// ---------------- scratch (device globals; no allocation allowed) ----------
__device__ float    g_x[kN * kD];
__device__ float    g_xl[kN * kD];
__device__ float    g_xr[kN * kD];
__device__ float    g_ea[(size_t)kEA * kEE];  // [0,E): edge emb, [E,E+N): loop attr
__device__ float    g_p[kEA * kH];            // logits, then p
__device__ unsigned g_m[kN * kH];             // encoded segment max
__device__ float    g_den[kN * kH];
__device__ float    g_hacc[kN * kD];
__device__ float    g_cnt[kN];
__device__ float    g_gsum[kG * kD];
__device__ float    g_gcnt[kG];

// monotone float <-> uint encoding for atomicMax on floats
__device__ __forceinline__ unsigned fenc(float f) {
    unsigned b = __float_as_uint(f);
    return (b & 0x80000000u) ? ~b : (b | 0x80000000u);
}
__device__ __forceinline__ float fdec(unsigned u) {
    unsigned b = (u & 0x80000000u) ? (u & 0x7fffffffu) : ~u;
    return __uint_as_float(b);
}

// ---------------- zero kernels ---------------------------------------------
__global__ void zero_init_kernel() {
    int i = blockIdx.x * blockDim.x + threadIdx.x;
    int stride = gridDim.x * blockDim.x;
    for (int t = i; t < kN * kEE; t += stride) g_ea[(size_t)kE * kEE + t] = 0.f;
    for (int t = i; t < kN; t += stride) g_cnt[t] = 0.f;
    for (int t = i; t < kG * kD; t += stride) g_gsum[t] = 0.f;
    for (int t = i; t < kG; t += stride) g_gcnt[t] = 0.f;
}
__global__ void zero_layer_kernel() {
    int i = blockIdx.x * blockDim.x + threadIdx.x;
    int stride = gridDim.x * blockDim.x;
    for (int t = i; t < kN * kD; t += stride) g_hacc[t] = 0.f;
    for (int t = i; t < kN * kH; t += stride) { g_m[t] = 0u; g_den[t] = 0.f; }
}

// ---------------- encoders -------------------------------------------------
__global__ void node_encode(const int* __restrict__ xn, const float* __restrict__ emb) {
    int t = blockIdx.x * blockDim.x + threadIdx.x;
    if (t >= kN * kD) return;
    int n = t >> 7, j = t & 127;
    g_x[t] = emb[xn[n] * kD + j];
}

// eattr = edge_attr @ edge_W + edge_b ; accumulate per-dst mean inputs
__global__ void edge_encode(const int* __restrict__ src, const int* __restrict__ dst,
                            const float* __restrict__ eat, const float* __restrict__ W,
                            const float* __restrict__ b) {
    int wid = (blockIdx.x * blockDim.x + threadIdx.x) >> 5;
    int lane = threadIdx.x & 31;
    if (wid >= kE) return;
    int e = wid;
    float a = (lane < kEF) ? eat[e * kEF + lane] : 0.f;
    int j0 = lane * 2;
    float acc0 = 0.f, acc1 = 0.f;
#pragma unroll
    for (int k = 0; k < kEF; k++) {
        float ak = __shfl_sync(0xffffffffu, a, k);
        float2 w = *(const float2*)(W + k * kEE + j0);
        acc0 += ak * w.x; acc1 += ak * w.y;
    }
    acc0 += b[j0]; acc1 += b[j0 + 1];
    *(float2*)(g_ea + (size_t)e * kEE + j0) = make_float2(acc0, acc1);
    int s = src[e], d = dst[e];
    if (s != d) {
        atomicAdd(&g_ea[((size_t)kE + d) * kEE + j0], acc0);
        atomicAdd(&g_ea[((size_t)kE + d) * kEE + j0 + 1], acc1);
        if (lane == 0) atomicAdd(&g_cnt[d], 1.f);
    }
}

__global__ void loop_fin() {
    int t = blockIdx.x * blockDim.x + threadIdx.x;
    if (t >= kN * kEE) return;
    int n = t >> 6;
    g_ea[(size_t)kE * kEE + t] /= fmaxf(g_cnt[n], 1.f);
}

// ---------------- per-layer node transforms: xl = x@Wl+bl, xr = x@Wr+br ----
__global__ void xlr_gemm(const float* __restrict__ Wl, const float* __restrict__ bl,
                         const float* __restrict__ Wr, const float* __restrict__ br,
                         int layer) {
    const float* W = (blockIdx.y == 0 ? Wl : Wr) + layer * kD * kD;
    const float* bias = (blockIdx.y == 0 ? bl : br) + layer * kD;
    float* out = blockIdx.y == 0 ? g_xl : g_xr;

    __shared__ __align__(16) float ws[32 * 128];
    __shared__ float xs[32][33];

    int t = threadIdx.x;     // 256 threads
    int cg = t & 31;         // columns cg*4 .. cg*4+3
    int ng = t >> 5;         // node group: nodes ng*4 .. ng*4+3
    int n0 = blockIdx.x * 32;

    float acc[4][4] = {};
    for (int kt = 0; kt < kD; kt += 32) {
#pragma unroll
        for (int r = t; r < 32 * 128; r += 256)
            ws[r] = W[(kt + (r >> 7)) * kD + (r & 127)];
#pragma unroll
        for (int r = t; r < 32 * 32; r += 256) {
            int n = r >> 5, kk = r & 31;
            int nn = n0 + n;
            xs[n][kk] = (nn < kN) ? g_x[nn * kD + kt + kk] : 0.f;
        }
        __syncthreads();
#pragma unroll
        for (int kk = 0; kk < 32; kk++) {
            float4 w = *(const float4*)&ws[kk * 128 + cg * 4];
#pragma unroll
            for (int m = 0; m < 4; m++) {
                float xv = xs[ng * 4 + m][kk];
                acc[m][0] += xv * w.x; acc[m][1] += xv * w.y;
                acc[m][2] += xv * w.z; acc[m][3] += xv * w.w;
            }
        }
        __syncthreads();
    }
    float4 bv = *(const float4*)(bias + cg * 4);
#pragma unroll
    for (int m = 0; m < 4; m++) {
        int n = n0 + ng * 4 + m;
        if (n < kN) {
            float4 o = make_float4(acc[m][0] + bv.x, acc[m][1] + bv.y,
                                   acc[m][2] + bv.z, acc[m][3] + bv.w);
            *(float4*)&out[n * kD + cg * 4] = o;
        }
    }
}

// ---------------- edge logits: ep GEMM fused + leaky_relu + att dot + max --
__global__ void edge_logits(const int* __restrict__ src, const int* __restrict__ dst,
                            const float* __restrict__ We, const float* __restrict__ att,
                            int layer) {
    __shared__ __align__(16) float ws[kEE * kD];   // 32 KB, We[layer]
    __shared__ __align__(16) float atts[kD];
    __shared__ __align__(16) float sa[32 * kEE];   // 8 KB, 32 edges' features

    int t = threadIdx.x, lane = t & 31, w = t >> 5;
    for (int r = t; r < kEE * kD; r += 256) ws[r] = We[layer * kEE * kD + r];
    if (t < kD) atts[t] = att[layer * kD + t];
    const float4* w4 = (const float4*)ws;

    int blockStart = blockIdx.x * 64;
    for (int half = 0; half < 2; half++) {
        int hbase = blockStart + half * 32;
        __syncthreads();
        for (int r = t; r < 32 * kEE; r += 256) {
            int e = hbase + (r >> 6);
            sa[r] = (e < kEA) ? g_ea[(size_t)e * kEE + (r & 63)] : 0.f;
        }
        __syncthreads();

        float4 acc[4] = {};
        const float* my = &sa[(w * 4) * kEE];
#pragma unroll 16
        for (int k = 0; k < kEE; k++) {
            float4 wv = w4[k * 32 + lane];
#pragma unroll
            for (int q = 0; q < 4; q++) {
                float ak = my[q * kEE + k];
                acc[q].x += ak * wv.x; acc[q].y += ak * wv.y;
                acc[q].z += ak * wv.z; acc[q].w += ak * wv.w;
            }
        }
#pragma unroll
        for (int q = 0; q < 4; q++) {
            int e = hbase + w * 4 + q;
            if (e >= kEA) continue;
            int s, d;
            if (e < kE) { s = src[e]; d = dst[e]; if (s == d) continue; }
            else { s = d = e - kE; }
            float4 xlv = *(const float4*)&g_xl[s * kD + lane * 4];
            float4 xrv = *(const float4*)&g_xr[d * kD + lane * 4];
            float zx = acc[q].x + xlv.x + xrv.x;
            float zy = acc[q].y + xlv.y + xrv.y;
            float zz = acc[q].z + xlv.z + xrv.z;
            float zw = acc[q].w + xlv.w + xrv.w;
            zx = fmaxf(zx, 0.2f * zx); zy = fmaxf(zy, 0.2f * zy);
            zz = fmaxf(zz, 0.2f * zz); zw = fmaxf(zw, 0.2f * zw);
            float4 av = *(const float4*)&atts[lane * 4];
            float part = zx * av.x + zy * av.y + zz * av.z + zw * av.w;
            part += __shfl_down_sync(0xffffffffu, part, 1);
            part += __shfl_down_sync(0xffffffffu, part, 2);
            if (!(lane & 3)) {
                int h = lane >> 2;
                g_p[e * kH + h] = part;
                atomicMax(&g_m[d * kH + h], fenc(part));
            }
        }
    }
}

// ---------------- softmax numerator + denominator --------------------------
__global__ void softmax_p(const int* __restrict__ src, const int* __restrict__ dst) {
    int tt = blockIdx.x * blockDim.x + threadIdx.x;
    if (tt >= kEA * kH) return;
    int e = tt >> 3, h = tt & 7;
    int d; bool masked = false;
    if (e < kE) { int s = src[e]; d = dst[e]; masked = (s == d); }
    else d = e - kE;
    float pv = 0.f;
    if (!masked) {
        float l = g_p[tt];
        float mv = fdec(g_m[d * kH + h]);
        pv = __expf(l - mv);
        atomicAdd(&g_den[d * kH + h], pv);
    }
    g_p[tt] = pv;
}

// ---------------- weighted aggregation: hacc[d] += alpha * xl[s] -----------
__global__ void aggregate(const int* __restrict__ src, const int* __restrict__ dst) {
    int wid = (blockIdx.x * blockDim.x + threadIdx.x) >> 5;
    int lane = threadIdx.x & 31;
    if (wid >= kEA) return;
    int e = wid, s, d;
    if (e < kE) { s = src[e]; d = dst[e]; if (s == d) return; }
    else { s = d = e - kE; }
    int h = lane >> 2;
    float p = g_p[e * kH + h];
    float den = g_den[d * kH + h];
    float alpha = p / den;
    float4 xlv = *(const float4*)&g_xl[s * kD + lane * 4];
    float* hp = &g_hacc[d * kD + lane * 4];
    atomicAdd(hp + 0, alpha * xlv.x);
    atomicAdd(hp + 1, alpha * xlv.y);
    atomicAdd(hp + 2, alpha * xlv.z);
    atomicAdd(hp + 3, alpha * xlv.w);
}

// ---------------- bias + BN(eval) + ELU ------------------------------------
__global__ void node_update(const float* __restrict__ gbias, const float* __restrict__ gam,
                            const float* __restrict__ bet, int layer) {
    int t = blockIdx.x * blockDim.x + threadIdx.x;
    if (t >= kN * kD) return;
    int j = t & 127;
    float v = g_hacc[t] + gbias[layer * kD + j];
    v = gam[layer * kD + j] * v * kBNS + bet[layer * kD + j];
    g_x[t] = v > 0.f ? v : expm1f(v);
}

// ---------------- global mean pool + linear head ---------------------------
__global__ void pool(const int* __restrict__ batch) {
    int wid = (blockIdx.x * blockDim.x + threadIdx.x) >> 5;
    int lane = threadIdx.x & 31;
    if (wid >= kN) return;
    int b = batch[wid];
    float4 xv = *(const float4*)&g_x[wid * kD + lane * 4];
    float* gp = &g_gsum[b * kD + lane * 4];
    atomicAdd(gp + 0, xv.x); atomicAdd(gp + 1, xv.y);
    atomicAdd(gp + 2, xv.z); atomicAdd(gp + 3, xv.w);
    if (lane == 0) atomicAdd(&g_gcnt[b], 1.f);
}

__global__ void head(const float* __restrict__ hW, const float* __restrict__ hb,
                     float* __restrict__ out) {
    int g = blockIdx.x;
    int lane = threadIdx.x;
    float cnt = fmaxf(g_gcnt[g], 1.f);
    float acc[kNC] = {};
    for (int k = lane; k < kD; k += 32) {
        float m = g_gsum[g * kD + k] / cnt;
#pragma unroll
        for (int c = 0; c < kNC; c++) acc[c] += m * hW[k * kNC + c];
    }
#pragma unroll
    for (int c = 0; c < kNC; c++) {
        float v = acc[c];
#pragma unroll
        for (int o = 16; o > 0; o >>= 1) v += __shfl_down_sync(0xffffffffu, v, o);
        if (lane == 0) out[g * kNC + c] = v + hb[c];
    }
}

// ---------------- launch ----------------------------------------------------
extern "C" void kernel_launch(void* const* d_in, const int* in_sizes, int n_in,
                              void* d_out, int out_size) {
    const int*   x_nodes = (const int*)d_in[0];
    const int*   esrc    = (const int*)d_in[1];
    const int*   edst    = (const int*)d_in[2];
    const float* eattr   = (const float*)d_in[3];
    const int*   batch   = (const int*)d_in[4];
    const float* nemb    = (const float*)d_in[5];
    const float* edge_W  = (const float*)d_in[6];
    const float* edge_b  = (const float*)d_in[7];
    const float* Wl      = (const float*)d_in[8];
    const float* bl      = (const float*)d_in[9];
    const float* Wr      = (const float*)d_in[10];
    const float* br      = (const float*)d_in[11];
    const float* We      = (const float*)d_in[12];
    const float* att     = (const float*)d_in[13];
    const float* gbias   = (const float*)d_in[14];
    const float* bng     = (const float*)d_in[15];
    const float* bnb     = (const float*)d_in[16];
    const float* headW   = (const float*)d_in[17];
    const float* headb   = (const float*)d_in[18];
    float* out = (float*)d_out;

    zero_init_kernel<<<2048, 256>>>();
    node_encode<<<(kN * kD + 255) / 256, 256>>>(x_nodes, nemb);
    edge_encode<<<(kE * 32 + 255) / 256, 256>>>(esrc, edst, eattr, edge_W, edge_b);
    loop_fin<<<(kN * kEE + 255) / 256, 256>>>();

    for (int i = 0; i < kL; i++) {
        zero_layer_kernel<<<4096, 256>>>();
        xlr_gemm<<<dim3((kN + 31) / 32, 2), 256>>>(Wl, bl, Wr, br, i);
        edge_logits<<<(kEA + 63) / 64, 256>>>(esrc, edst, We, att, i);
        softmax_p<<<(kEA * kH + 255) / 256, 256>>>(esrc, edst);
        aggregate<<<(int)(((long long)kEA * 32 + 255) / 256), 256>>>(esrc, edst);
        node_update<<<(kN * kD + 255) / 256, 256>>>(gbias, bng, bnb, i);
    }

    pool<<<(kN * 32 + 255) / 256, 256>>>(batch);
    head<<<kG, 32>>>(headW, headb, out);
}

// round 2
// speedup vs baseline: 2.5802x; 2.5802x over previous
#include <cuda_runtime.h>
#include <math.h>

// Problem constants
constexpr int kN   = 50000;
constexpr int kE   = 800000;
constexpr int kG   = 512;
constexpr int kD   = 128;
constexpr int kEE  = 64;
constexpr int kL   = 4;
constexpr int kNC  = 10;
constexpr int kSB  = (kN + 1023) / 1024;   // scan blocks
constexpr float kBNS = 0.9999950000374997f;  // (1+1e-5)^-0.5

// ---------------- scratch (device globals) ---------------------------------
__device__ float g_x[kN * kD];
__device__ float g_xl[kN * kD];
__device__ float g_xr[kN * kD];
__device__ float g_lraw[kN * 8];      // per-node mean of raw edge attrs
__device__ int   g_deg[kN];
__device__ int   g_cur[kN];
__device__ int   g_scan[kN];
__device__ int   g_bt[kSB];
__device__ int   g_boff[kSB];
__device__ int   g_off[kN + 1];
__device__ int   g_csrc[kE];          // CSR by dst: source node
__device__ int   g_ceid[kE];          // CSR by dst: original edge id
__device__ float g_M[8 * kD];         // edge_W @ We[layer]  (8 x 128)
__device__ float g_bep[kD];           // edge_b @ We[layer]
__device__ float g_gsum[kG * kD];
__device__ float g_gcnt[kG];

// ---------------- init ------------------------------------------------------
__global__ void zero_init_kernel() {
    int i = blockIdx.x * blockDim.x + threadIdx.x;
    int stride = gridDim.x * blockDim.x;
    for (int t = i; t < kN * 8; t += stride) g_lraw[t] = 0.f;
    for (int t = i; t < kN; t += stride) { g_deg[t] = 0; g_cur[t] = 0; }
    for (int t = i; t < kG * kD; t += stride) g_gsum[t] = 0.f;
    for (int t = i; t < kG; t += stride) g_gcnt[t] = 0.f;
}

__global__ void node_encode(const int* __restrict__ xn, const float* __restrict__ emb) {
    int t = blockIdx.x * blockDim.x + threadIdx.x;
    if (t >= kN * kD) return;
    int n = t >> 7, j = t & 127;
    g_x[t] = emb[xn[n] * kD + j];
}

// per-dst in-degree (excluding self loops) + raw attr sums
__global__ void count_deg(const int* __restrict__ src, const int* __restrict__ dst,
                          const float* __restrict__ eat) {
    int t = blockIdx.x * blockDim.x + threadIdx.x;
    if (t >= kE * 8) return;
    int e = t >> 3, j = t & 7;
    int s = src[e], d = dst[e];
    if (s == d) return;
    atomicAdd(&g_lraw[d * 8 + j], eat[t]);
    if (j == 0) atomicAdd(&g_deg[d], 1);
}

__global__ void lraw_fin() {
    int t = blockIdx.x * blockDim.x + threadIdx.x;
    if (t >= kN * 8) return;
    int n = t >> 3;
    int c = g_deg[n];
    g_lraw[t] /= (float)(c > 1 ? c : 1);
}

// ---------------- exclusive scan of deg -> off ------------------------------
__global__ void scan1() {
    __shared__ int sh[1024];
    int n = blockIdx.x * 1024 + threadIdx.x;
    int v = (n < kN) ? g_deg[n] : 0;
    sh[threadIdx.x] = v;
    __syncthreads();
    for (int o = 1; o < 1024; o <<= 1) {
        int add = (threadIdx.x >= o) ? sh[threadIdx.x - o] : 0;
        __syncthreads();
        sh[threadIdx.x] += add;
        __syncthreads();
    }
    if (n < kN) g_scan[n] = sh[threadIdx.x];
    if (threadIdx.x == 1023) g_bt[blockIdx.x] = sh[1023];
}
__global__ void scan2() {
    if (threadIdx.x == 0) {
        int run = 0;
        for (int b = 0; b < kSB; b++) { g_boff[b] = run; run += g_bt[b]; }
        g_off[kN] = run;
    }
}
__global__ void scan3() {
    int n = blockIdx.x * blockDim.x + threadIdx.x;
    if (n < kN) g_off[n] = g_scan[n] - g_deg[n] + g_boff[n >> 10];
}

__global__ void scatter_csr(const int* __restrict__ src, const int* __restrict__ dst) {
    int e = blockIdx.x * blockDim.x + threadIdx.x;
    if (e >= kE) return;
    int s = src[e], d = dst[e];
    if (s == d) return;
    int pos = atomicAdd(&g_cur[d], 1);
    int idx = g_off[d] + pos;
    g_csrc[idx] = s;
    g_ceid[idx] = e;
}

// ---------------- per-layer: M = edge_W @ We[layer], bep = edge_b @ We ------
__global__ void make_M(const float* __restrict__ eW, const float* __restrict__ eb,
                       const float* __restrict__ We, int layer) {
    int t = threadIdx.x;          // 1024
    int k = t >> 7, j = t & 127;
    const float* w = We + (size_t)layer * kEE * kD;
    float acc = 0.f;
#pragma unroll 8
    for (int u = 0; u < kEE; u++) acc += eW[k * kEE + u] * w[u * kD + j];
    g_M[k * kD + j] = acc;
    if (t < kD) {
        float b = 0.f;
#pragma unroll 8
        for (int u = 0; u < kEE; u++) b += eb[u] * w[u * kD + t];
        g_bep[t] = b;
    }
}

// ---------------- xl = x@Wl+bl, xr = x@Wr+br --------------------------------
__global__ void xlr_gemm(const float* __restrict__ Wl, const float* __restrict__ bl,
                         const float* __restrict__ Wr, const float* __restrict__ br,
                         int layer) {
    const float* W = (blockIdx.y == 0 ? Wl : Wr) + layer * kD * kD;
    const float* bias = (blockIdx.y == 0 ? bl : br) + layer * kD;
    float* out = blockIdx.y == 0 ? g_xl : g_xr;

    __shared__ __align__(16) float ws[32 * 128];
    __shared__ float xs[32][33];

    int t = threadIdx.x;
    int cg = t & 31;
    int ng = t >> 5;
    int n0 = blockIdx.x * 32;

    float acc[4][4] = {};
    for (int kt = 0; kt < kD; kt += 32) {
        for (int r = t; r < 32 * 128; r += 256)
            ws[r] = W[(kt + (r >> 7)) * kD + (r & 127)];
        for (int r = t; r < 32 * 32; r += 256) {
            int n = r >> 5, kk = r & 31;
            int nn = n0 + n;
            xs[n][kk] = (nn < kN) ? g_x[nn * kD + kt + kk] : 0.f;
        }
        __syncthreads();
#pragma unroll
        for (int kk = 0; kk < 32; kk++) {
            float4 w = *(const float4*)&ws[kk * 128 + cg * 4];
#pragma unroll
            for (int m = 0; m < 4; m++) {
                float xv = xs[ng * 4 + m][kk];
                acc[m][0] += xv * w.x; acc[m][1] += xv * w.y;
                acc[m][2] += xv * w.z; acc[m][3] += xv * w.w;
            }
        }
        __syncthreads();
    }
    float4 bv = *(const float4*)(bias + cg * 4);
#pragma unroll
    for (int m = 0; m < 4; m++) {
        int n = n0 + ng * 4 + m;
        if (n < kN) {
            float4 o = make_float4(acc[m][0] + bv.x, acc[m][1] + bv.y,
                                   acc[m][2] + bv.z, acc[m][3] + bv.w);
            *(float4*)&out[n * kD + cg * 4] = o;
        }
    }
}

// ---------------- fused GAT layer: logits + online softmax + agg + update ---
__global__ __launch_bounds__(256) void fused_gat(
        const float* __restrict__ eattr, const float* __restrict__ att,
        const float* __restrict__ gbias, const float* __restrict__ gam,
        const float* __restrict__ bet, int layer) {
    __shared__ __align__(16) float Ms[8 * kD];
    __shared__ __align__(16) float atts[kD];
    __shared__ __align__(16) float beps[kD];

    int t = threadIdx.x;
    for (int r = t; r < 8 * kD; r += 256) Ms[r] = g_M[r];
    if (t < kD) { atts[t] = att[layer * kD + t]; beps[t] = g_bep[t]; }
    __syncthreads();

    int d = (blockIdx.x * 256 + t) >> 5;
    if (d >= kN) return;
    int lane = t & 31;
    int j0 = lane * 4;

    float4 attv = *(const float4*)&atts[j0];
    float4 bep4 = *(const float4*)&beps[j0];
    float4 xr4  = *(const float4*)&g_xr[d * kD + j0];

    // ---- self loop (always present, starts online softmax state) ----
    float rv = (lane < 8) ? g_lraw[d * 8 + lane] : 0.f;
    float4 ep = bep4;
#pragma unroll
    for (int k = 0; k < 8; k++) {
        float rk = __shfl_sync(0xffffffffu, rv, k);
        float4 mv = *(const float4*)&Ms[k * kD + j0];
        ep.x += rk * mv.x; ep.y += rk * mv.y;
        ep.z += rk * mv.z; ep.w += rk * mv.w;
    }
    float4 xld = *(const float4*)&g_xl[d * kD + j0];
    float zx = xld.x + xr4.x + ep.x; zx = fmaxf(zx, 0.2f * zx);
    float zy = xld.y + xr4.y + ep.y; zy = fmaxf(zy, 0.2f * zy);
    float zz = xld.z + xr4.z + ep.z; zz = fmaxf(zz, 0.2f * zz);
    float zw = xld.w + xr4.w + ep.w; zw = fmaxf(zw, 0.2f * zw);
    float l = zx * attv.x + zy * attv.y + zz * attv.z + zw * attv.w;
    l += __shfl_xor_sync(0xffffffffu, l, 1);
    l += __shfl_xor_sync(0xffffffffu, l, 2);

    float m = l, den = 1.f;
    float4 acc = xld;

    int beg = g_off[d], end = g_off[d + 1];
    for (int idx = beg; idx < end; idx++) {
        int s = g_csrc[idx];
        int e = g_ceid[idx];
        float4 xls = *(const float4*)&g_xl[s * kD + j0];   // issue gather early
        float r2 = (lane < 8) ? eattr[(size_t)e * 8 + lane] : 0.f;
        float4 ep2 = bep4;
#pragma unroll
        for (int k = 0; k < 8; k++) {
            float rk = __shfl_sync(0xffffffffu, r2, k);
            float4 mv = *(const float4*)&Ms[k * kD + j0];
            ep2.x += rk * mv.x; ep2.y += rk * mv.y;
            ep2.z += rk * mv.z; ep2.w += rk * mv.w;
        }
        float ax = xls.x + xr4.x + ep2.x; ax = fmaxf(ax, 0.2f * ax);
        float ay = xls.y + xr4.y + ep2.y; ay = fmaxf(ay, 0.2f * ay);
        float az = xls.z + xr4.z + ep2.z; az = fmaxf(az, 0.2f * az);
        float aw = xls.w + xr4.w + ep2.w; aw = fmaxf(aw, 0.2f * aw);
        float l2 = ax * attv.x + ay * attv.y + az * attv.z + aw * attv.w;
        l2 += __shfl_xor_sync(0xffffffffu, l2, 1);
        l2 += __shfl_xor_sync(0xffffffffu, l2, 2);

        float nm = fmaxf(m, l2);
        float sc = __expf(m - nm);
        float p  = __expf(l2 - nm);
        m = nm;
        den = den * sc + p;
        acc.x = acc.x * sc + p * xls.x;
        acc.y = acc.y * sc + p * xls.y;
        acc.z = acc.z * sc + p * xls.z;
        acc.w = acc.w * sc + p * xls.w;
    }

    float inv = 1.f / den;
    float4 gb = *(const float4*)&gbias[layer * kD + j0];
    float4 gm = *(const float4*)&gam[layer * kD + j0];
    float4 bt = *(const float4*)&bet[layer * kD + j0];
    float v0 = gm.x * (acc.x * inv + gb.x) * kBNS + bt.x;
    float v1 = gm.y * (acc.y * inv + gb.y) * kBNS + bt.y;
    float v2 = gm.z * (acc.z * inv + gb.z) * kBNS + bt.z;
    float v3 = gm.w * (acc.w * inv + gb.w) * kBNS + bt.w;
    float4 o;
    o.x = v0 > 0.f ? v0 : expm1f(v0);
    o.y = v1 > 0.f ? v1 : expm1f(v1);
    o.z = v2 > 0.f ? v2 : expm1f(v2);
    o.w = v3 > 0.f ? v3 : expm1f(v3);
    *(float4*)&g_x[d * kD + j0] = o;
}

// ---------------- pool + head ----------------------------------------------
__global__ void pool(const int* __restrict__ batch) {
    int wid = (blockIdx.x * blockDim.x + threadIdx.x) >> 5;
    int lane = threadIdx.x & 31;
    if (wid >= kN) return;
    int b = batch[wid];
    float4 xv = *(const float4*)&g_x[wid * kD + lane * 4];
    float* gp = &g_gsum[b * kD + lane * 4];
    atomicAdd(gp + 0, xv.x); atomicAdd(gp + 1, xv.y);
    atomicAdd(gp + 2, xv.z); atomicAdd(gp + 3, xv.w);
    if (lane == 0) atomicAdd(&g_gcnt[b], 1.f);
}

__global__ void head(const float* __restrict__ hW, const float* __restrict__ hb,
                     float* __restrict__ out) {
    int g = blockIdx.x;
    int lane = threadIdx.x;
    float cnt = fmaxf(g_gcnt[g], 1.f);
    float acc[kNC] = {};
    for (int k = lane; k < kD; k += 32) {
        float mm = g_gsum[g * kD + k] / cnt;
#pragma unroll
        for (int c = 0; c < kNC; c++) acc[c] += mm * hW[k * kNC + c];
    }
#pragma unroll
    for (int c = 0; c < kNC; c++) {
        float v = acc[c];
#pragma unroll
        for (int o = 16; o > 0; o >>= 1) v += __shfl_down_sync(0xffffffffu, v, o);
        if (lane == 0) out[g * kNC + c] = v + hb[c];
    }
}

// ---------------- launch ----------------------------------------------------
extern "C" void kernel_launch(void* const* d_in, const int* in_sizes, int n_in,
                              void* d_out, int out_size) {
    const int*   x_nodes = (const int*)d_in[0];
    const int*   esrc    = (const int*)d_in[1];
    const int*   edst    = (const int*)d_in[2];
    const float* eattr   = (const float*)d_in[3];
    const int*   batch   = (const int*)d_in[4];
    const float* nemb    = (const float*)d_in[5];
    const float* edge_W  = (const float*)d_in[6];
    const float* edge_b  = (const float*)d_in[7];
    const float* Wl      = (const float*)d_in[8];
    const float* bl      = (const float*)d_in[9];
    const float* Wr      = (const float*)d_in[10];
    const float* br      = (const float*)d_in[11];
    const float* We      = (const float*)d_in[12];
    const float* att     = (const float*)d_in[13];
    const float* gbias   = (const float*)d_in[14];
    const float* bng     = (const float*)d_in[15];
    const float* bnb     = (const float*)d_in[16];
    const float* headW   = (const float*)d_in[17];
    const float* headb   = (const float*)d_in[18];
    float* out = (float*)d_out;

    zero_init_kernel<<<1024, 256>>>();
    node_encode<<<(kN * kD + 255) / 256, 256>>>(x_nodes, nemb);
    count_deg<<<(kE * 8 + 255) / 256, 256>>>(esrc, edst, eattr);
    lraw_fin<<<(kN * 8 + 255) / 256, 256>>>();
    scan1<<<kSB, 1024>>>();
    scan2<<<1, 32>>>();
    scan3<<<(kN + 255) / 256, 256>>>();
    scatter_csr<<<(kE + 255) / 256, 256>>>(esrc, edst);

    for (int i = 0; i < kL; i++) {
        make_M<<<1, 1024>>>(edge_W, edge_b, We, i);
        xlr_gemm<<<dim3((kN + 31) / 32, 2), 256>>>(Wl, bl, Wr, br, i);
        fused_gat<<<(kN * 32 + 255) / 256, 256>>>(eattr, att, gbias, bng, bnb, i);
    }

    pool<<<(kN * 32 + 255) / 256, 256>>>(batch);
    head<<<kG, 32>>>(headW, headb, out);
}